// round 1
// baseline (speedup 1.0000x reference)
#include <cuda_runtime.h>

#define Nn 50000
#define Dd 128
#define Ee 800000
#define EPS_LN 1e-5f
#define SQRT_D 11.313708498984761f

// Scratch (static device globals — allocation-free per harness rules)
__device__ float g_x[Nn * Dd];    // 25.6 MB
__device__ float g_agg[Nn * Dd];  // 25.6 MB

// ---------------------------------------------------------------------------
// Kernel 1: x = LayerNorm(node_emb * sqrt(D) + pos_table[pos])
// One warp per row, 4 floats per lane.
// ---------------------------------------------------------------------------
__global__ void embed_ln_kernel(const float* __restrict__ ne,
                                const int* __restrict__ pos,
                                const float* __restrict__ ptab,
                                const float* __restrict__ g,
                                const float* __restrict__ b) {
    int w    = (blockIdx.x * blockDim.x + threadIdx.x) >> 5;
    int lane = threadIdx.x & 31;
    if (w >= Nn) return;
    int p = pos[w];
    float4 nv = *(const float4*)(ne   + (size_t)w * Dd + lane * 4);
    float4 pv = *(const float4*)(ptab + (size_t)p * Dd + lane * 4);
    float v0 = fmaf(nv.x, SQRT_D, pv.x);
    float v1 = fmaf(nv.y, SQRT_D, pv.y);
    float v2 = fmaf(nv.z, SQRT_D, pv.z);
    float v3 = fmaf(nv.w, SQRT_D, pv.w);
    float s = v0 + v1 + v2 + v3;
    float q = v0 * v0 + v1 * v1 + v2 * v2 + v3 * v3;
#pragma unroll
    for (int m = 1; m < 32; m <<= 1) {
        s += __shfl_xor_sync(0xffffffffu, s, m);
        q += __shfl_xor_sync(0xffffffffu, q, m);
    }
    float mean = s * (1.0f / 128.0f);
    float rstd = rsqrtf(q * (1.0f / 128.0f) - mean * mean + EPS_LN);
    float4 gv = *(const float4*)(g + lane * 4);
    float4 bv = *(const float4*)(b + lane * 4);
    float4 o;
    o.x = (v0 - mean) * rstd * gv.x + bv.x;
    o.y = (v1 - mean) * rstd * gv.y + bv.y;
    o.z = (v2 - mean) * rstd * gv.z + bv.z;
    o.w = (v3 - mean) * rstd * gv.w + bv.w;
    *(float4*)(g_x + (size_t)w * Dd + lane * 4) = o;
}

// ---------------------------------------------------------------------------
// Kernel 2: zero agg
// ---------------------------------------------------------------------------
__global__ void zero_agg_kernel() {
    int i = blockIdx.x * blockDim.x + threadIdx.x;  // Nn*Dd/4 = 1,600,000 float4
    if (i < Nn * Dd / 4) {
        float4 z = make_float4(0.f, 0.f, 0.f, 0.f);
        ((float4*)g_agg)[i] = z;
    }
}

// ---------------------------------------------------------------------------
// Kernel 3: agg[dst] += x[src]   (one warp per edge, vector f32x4 RED)
// ---------------------------------------------------------------------------
__global__ void scatter_kernel(const int* __restrict__ edge) {
    int w    = (blockIdx.x * blockDim.x + threadIdx.x) >> 5;
    int lane = threadIdx.x & 31;
    if (w >= Ee) return;
    int src = __ldg(edge + w);
    int dst = __ldg(edge + Ee + w);
    float4 v = *(const float4*)(g_x + (size_t)src * Dd + lane * 4);
    float* p = g_agg + (size_t)dst * Dd + lane * 4;
    asm volatile("red.global.add.v4.f32 [%0], {%1, %2, %3, %4};"
                 :: "l"(p), "f"(v.x), "f"(v.y), "f"(v.z), "f"(v.w)
                 : "memory");
}

// ---------------------------------------------------------------------------
// Kernel 4: fused dual-GEMM + bias + ReLU + residual + LayerNorm
//   h = relu(agg @ Wl + bl + x @ Wr); x_new = LN(h + x)
// Block: 256 threads, tile 64 rows x 128 cols, K = 256 (agg then x).
// Thread (tr = t>>4, tc = t&15) owns 4 rows x 8 cols.
// LN done fully in registers via 16-lane shfl reductions.
// ---------------------------------------------------------------------------
__global__ void __launch_bounds__(256)
gemm_ln_kernel(const float* __restrict__ Wl, const float* __restrict__ bl,
               const float* __restrict__ Wr, const float* __restrict__ lng,
               const float* __restrict__ lnb, float* __restrict__ dout,
               int writeOut) {
    __shared__ float As[64 * 16];
    __shared__ float Bs[16 * 128];

    int t    = threadIdx.x;
    int tc   = t & 15;
    int tr   = t >> 4;
    int row0 = blockIdx.x * 64;

    float acc[4][8];
#pragma unroll
    for (int i = 0; i < 4; ++i)
#pragma unroll
        for (int j = 0; j < 8; ++j) acc[i][j] = 0.f;

    int lrA = t >> 2;          // 0..63 (A load row)
    int lcA = (t & 3) * 4;     // 0,4,8,12 (A load col)
    int lrB = t >> 4;          // 0..15 (B load k-row)
    int lcB = (t & 15) * 8;    // B load col
    int gra = row0 + lrA;

    for (int ch = 0; ch < 16; ++ch) {
        int k0 = ch * 16;
        const float* A = (k0 < 128) ? g_agg : g_x;
        const float* W = (k0 < 128) ? Wl : Wr;
        int ka = k0 & 127;

        float4 av = make_float4(0.f, 0.f, 0.f, 0.f);
        if (gra < Nn) av = *(const float4*)(A + (size_t)gra * Dd + ka + lcA);
        *(float4*)(As + lrA * 16 + lcA) = av;

        const float* wrow = W + (size_t)(ka + lrB) * Dd + lcB;
        *(float4*)(Bs + lrB * 128 + lcB)     = *(const float4*)(wrow);
        *(float4*)(Bs + lrB * 128 + lcB + 4) = *(const float4*)(wrow + 4);
        __syncthreads();

#pragma unroll
        for (int kl = 0; kl < 16; ++kl) {
            float a[4];
#pragma unroll
            for (int i = 0; i < 4; ++i) a[i] = As[(tr * 4 + i) * 16 + kl];
            float4 b0 = *(float4*)(Bs + kl * 128 + tc * 8);
            float4 b1 = *(float4*)(Bs + kl * 128 + tc * 8 + 4);
            float bb[8] = {b0.x, b0.y, b0.z, b0.w, b1.x, b1.y, b1.z, b1.w};
#pragma unroll
            for (int i = 0; i < 4; ++i)
#pragma unroll
                for (int j = 0; j < 8; ++j)
                    acc[i][j] = fmaf(a[i], bb[j], acc[i][j]);
        }
        __syncthreads();
    }

    // --------------------- Epilogue: bias + relu + residual + LN -----------
    int cbase = tc * 8;
    float bb[8], gg[8], bt[8];
    {
        float4 u0 = *(const float4*)(bl + cbase);
        float4 u1 = *(const float4*)(bl + cbase + 4);
        bb[0]=u0.x; bb[1]=u0.y; bb[2]=u0.z; bb[3]=u0.w;
        bb[4]=u1.x; bb[5]=u1.y; bb[6]=u1.z; bb[7]=u1.w;
        float4 g0 = *(const float4*)(lng + cbase);
        float4 g1 = *(const float4*)(lng + cbase + 4);
        gg[0]=g0.x; gg[1]=g0.y; gg[2]=g0.z; gg[3]=g0.w;
        gg[4]=g1.x; gg[5]=g1.y; gg[6]=g1.z; gg[7]=g1.w;
        float4 t0 = *(const float4*)(lnb + cbase);
        float4 t1 = *(const float4*)(lnb + cbase + 4);
        bt[0]=t0.x; bt[1]=t0.y; bt[2]=t0.z; bt[3]=t0.w;
        bt[4]=t1.x; bt[5]=t1.y; bt[6]=t1.z; bt[7]=t1.w;
    }
    float* outp = writeOut ? dout : g_x;

#pragma unroll
    for (int i = 0; i < 4; ++i) {
        int r = row0 + tr * 4 + i;
        float xo[8];
        if (r < Nn) {
            float4 x0 = *(const float4*)(g_x + (size_t)r * Dd + cbase);
            float4 x1 = *(const float4*)(g_x + (size_t)r * Dd + cbase + 4);
            xo[0]=x0.x; xo[1]=x0.y; xo[2]=x0.z; xo[3]=x0.w;
            xo[4]=x1.x; xo[5]=x1.y; xo[6]=x1.z; xo[7]=x1.w;
        } else {
#pragma unroll
            for (int j = 0; j < 8; ++j) xo[j] = 0.f;
        }
        float s = 0.f, q = 0.f;
#pragma unroll
        for (int j = 0; j < 8; ++j) {
            float h = acc[i][j] + bb[j];
            h = fmaxf(h, 0.f);
            h += xo[j];
            acc[i][j] = h;
            s += h;
            q += h * h;
        }
#pragma unroll
        for (int m = 1; m < 16; m <<= 1) {
            s += __shfl_xor_sync(0xffffffffu, s, m);
            q += __shfl_xor_sync(0xffffffffu, q, m);
        }
        float mean = s * (1.0f / 128.0f);
        float rstd = rsqrtf(q * (1.0f / 128.0f) - mean * mean + EPS_LN);
        if (r < Nn) {
            float4 o0, o1;
            o0.x = (acc[i][0] - mean) * rstd * gg[0] + bt[0];
            o0.y = (acc[i][1] - mean) * rstd * gg[1] + bt[1];
            o0.z = (acc[i][2] - mean) * rstd * gg[2] + bt[2];
            o0.w = (acc[i][3] - mean) * rstd * gg[3] + bt[3];
            o1.x = (acc[i][4] - mean) * rstd * gg[4] + bt[4];
            o1.y = (acc[i][5] - mean) * rstd * gg[5] + bt[5];
            o1.z = (acc[i][6] - mean) * rstd * gg[6] + bt[6];
            o1.w = (acc[i][7] - mean) * rstd * gg[7] + bt[7];
            *(float4*)(outp + (size_t)r * Dd + cbase)     = o0;
            *(float4*)(outp + (size_t)r * Dd + cbase + 4) = o1;
        }
    }
}

// ---------------------------------------------------------------------------
extern "C" void kernel_launch(void* const* d_in, const int* in_sizes, int n_in,
                              void* d_out, int out_size) {
    const float* node_emb  = (const float*)d_in[0];
    const int*   pos       = (const int*)d_in[1];
    const int*   edge      = (const int*)d_in[2];
    const float* pos_table = (const float*)d_in[3];
    const float* Wl        = (const float*)d_in[4];
    const float* bl        = (const float*)d_in[5];
    const float* Wr        = (const float*)d_in[6];
    const float* emb_g     = (const float*)d_in[7];
    const float* emb_b     = (const float*)d_in[8];
    const float* hid_g     = (const float*)d_in[9];
    const float* hid_b     = (const float*)d_in[10];
    float* out = (float*)d_out;

    // embed + LN : one warp per row
    embed_ln_kernel<<<(Nn * 32 + 255) / 256, 256>>>(node_emb, pos, pos_table,
                                                    emb_g, emb_b);

    const int gemm_blocks = (Nn + 63) / 64;  // 782
    for (int l = 0; l < 3; ++l) {
        zero_agg_kernel<<<(Nn * Dd / 4 + 255) / 256, 256>>>();
        scatter_kernel<<<(Ee * 32 + 255) / 256, 256>>>(edge);
        gemm_ln_kernel<<<gemm_blocks, 256>>>(Wl + (size_t)l * Dd * Dd,
                                             bl + (size_t)l * Dd,
                                             Wr + (size_t)l * Dd * Dd,
                                             hid_g + (size_t)l * Dd,
                                             hid_b + (size_t)l * Dd,
                                             out, l == 2 ? 1 : 0);
    }
}

// round 2
// speedup vs baseline: 1.4600x; 1.4600x over previous
#include <cuda_runtime.h>

#define Nn 50000
#define Dd 128
#define Ee 800000
#define EPS_LN 1e-5f
#define SQRT_D 11.313708498984761f

// Scratch (static device globals — allocation-free per harness rules)
__device__ float g_x[Nn * Dd];    // 25.6 MB
__device__ float g_agg[Nn * Dd];  // 25.6 MB
__device__ int   g_deg[Nn];
__device__ int   g_rp[Nn + 1];
__device__ int   g_cur[Nn];
__device__ int   g_col[Ee];

// ---------------------------------------------------------------------------
// Kernel 1: x = LayerNorm(node_emb * sqrt(D) + pos_table[pos])
// ---------------------------------------------------------------------------
__global__ void embed_ln_kernel(const float* __restrict__ ne,
                                const int* __restrict__ pos,
                                const float* __restrict__ ptab,
                                const float* __restrict__ g,
                                const float* __restrict__ b) {
    int w    = (blockIdx.x * blockDim.x + threadIdx.x) >> 5;
    int lane = threadIdx.x & 31;
    if (w >= Nn) return;
    int p = pos[w];
    float4 nv = *(const float4*)(ne   + (size_t)w * Dd + lane * 4);
    float4 pv = *(const float4*)(ptab + (size_t)p * Dd + lane * 4);
    float v0 = fmaf(nv.x, SQRT_D, pv.x);
    float v1 = fmaf(nv.y, SQRT_D, pv.y);
    float v2 = fmaf(nv.z, SQRT_D, pv.z);
    float v3 = fmaf(nv.w, SQRT_D, pv.w);
    float s = v0 + v1 + v2 + v3;
    float q = v0 * v0 + v1 * v1 + v2 * v2 + v3 * v3;
#pragma unroll
    for (int m = 1; m < 32; m <<= 1) {
        s += __shfl_xor_sync(0xffffffffu, s, m);
        q += __shfl_xor_sync(0xffffffffu, q, m);
    }
    float mean = s * (1.0f / 128.0f);
    float rstd = rsqrtf(q * (1.0f / 128.0f) - mean * mean + EPS_LN);
    float4 gv = *(const float4*)(g + lane * 4);
    float4 bv = *(const float4*)(b + lane * 4);
    float4 o;
    o.x = (v0 - mean) * rstd * gv.x + bv.x;
    o.y = (v1 - mean) * rstd * gv.y + bv.y;
    o.z = (v2 - mean) * rstd * gv.z + bv.z;
    o.w = (v3 - mean) * rstd * gv.w + bv.w;
    *(float4*)(g_x + (size_t)w * Dd + lane * 4) = o;
}

// ---------------------------------------------------------------------------
// CSR build (once per call): deg histogram -> exclusive scan -> column fill
// ---------------------------------------------------------------------------
__global__ void zero_deg_kernel() {
    int i = blockIdx.x * blockDim.x + threadIdx.x;
    if (i < Nn) g_deg[i] = 0;
}

__global__ void hist_kernel(const int* __restrict__ edge) {
    int e = blockIdx.x * blockDim.x + threadIdx.x;
    if (e < Ee) atomicAdd(&g_deg[edge[Ee + e]], 1);
}

// Single-block exclusive scan of g_deg -> g_rp (and g_cur copy).
__global__ void __launch_bounds__(1024) build_rowptr_kernel() {
    __shared__ int ts[1024];
    const int CH = (Nn + 1023) / 1024;  // 49
    int t = threadIdx.x;
    int base = t * CH;
    int s = 0;
    for (int i = 0; i < CH; ++i) {
        int idx = base + i;
        if (idx < Nn) s += g_deg[idx];
    }
    ts[t] = s;
    __syncthreads();
    // inclusive Hillis-Steele scan
    for (int off = 1; off < 1024; off <<= 1) {
        int u = (t >= off) ? ts[t - off] : 0;
        __syncthreads();
        ts[t] += u;
        __syncthreads();
    }
    int run = ts[t] - s;  // exclusive prefix for this chunk
    for (int i = 0; i < CH; ++i) {
        int idx = base + i;
        if (idx < Nn) {
            g_rp[idx]  = run;
            g_cur[idx] = run;
            run += g_deg[idx];
        }
    }
    if (t == 1023) g_rp[Nn] = Ee;
}

__global__ void fill_csr_kernel(const int* __restrict__ edge) {
    int e = blockIdx.x * blockDim.x + threadIdx.x;
    if (e < Ee) {
        int src = edge[e];
        int dst = edge[Ee + e];
        int p = atomicAdd(&g_cur[dst], 1);
        g_col[p] = src;
    }
}

// ---------------------------------------------------------------------------
// Aggregate: agg[i] = sum_{j in CSR row i} x[col[j]]   (one warp per row)
// ---------------------------------------------------------------------------
__global__ void aggregate_kernel() {
    int w    = (blockIdx.x * blockDim.x + threadIdx.x) >> 5;
    int lane = threadIdx.x & 31;
    if (w >= Nn) return;
    int beg = g_rp[w];
    int end = g_rp[w + 1];
    float4 a0 = make_float4(0.f, 0.f, 0.f, 0.f);
    float4 a1 = make_float4(0.f, 0.f, 0.f, 0.f);
    int jb = beg;
    while (jb < end) {
        int take = min(32, end - jb);
        int myc = (lane < take) ? __ldg(&g_col[jb + lane]) : 0;
        int u = 0;
        for (; u + 1 < take; u += 2) {
            int s0 = __shfl_sync(0xffffffffu, myc, u);
            int s1 = __shfl_sync(0xffffffffu, myc, u + 1);
            float4 v0 = *(const float4*)(g_x + (size_t)s0 * Dd + lane * 4);
            float4 v1 = *(const float4*)(g_x + (size_t)s1 * Dd + lane * 4);
            a0.x += v0.x; a0.y += v0.y; a0.z += v0.z; a0.w += v0.w;
            a1.x += v1.x; a1.y += v1.y; a1.z += v1.z; a1.w += v1.w;
        }
        if (u < take) {
            int s0 = __shfl_sync(0xffffffffu, myc, u);
            float4 v0 = *(const float4*)(g_x + (size_t)s0 * Dd + lane * 4);
            a0.x += v0.x; a0.y += v0.y; a0.z += v0.z; a0.w += v0.w;
        }
        jb += take;
    }
    float4 o;
    o.x = a0.x + a1.x; o.y = a0.y + a1.y; o.z = a0.z + a1.z; o.w = a0.w + a1.w;
    *(float4*)(g_agg + (size_t)w * Dd + lane * 4) = o;
}

// ---------------------------------------------------------------------------
// Fused dual-GEMM + bias + ReLU + residual + LayerNorm
//   h = relu(agg @ Wl + bl + x @ Wr); x_new = LN(h + x)
// 128x128 block tile, 256 threads, 8x8 thread tile, K=256 in 32 chunks of 8.
// As staged transposed [k][row] with pad-132; double-buffered smem.
// Thread (tr=t>>4, tc=t&15): rows tr*8..+7, cols {tc*4..+3} u {64+tc*4..+3}.
// ---------------------------------------------------------------------------
__global__ void __launch_bounds__(256, 2)
gemm_ln_kernel(const float* __restrict__ Wl, const float* __restrict__ bl,
               const float* __restrict__ Wr, const float* __restrict__ lng,
               const float* __restrict__ lnb, float* __restrict__ dout,
               int writeOut) {
    __shared__ float As[2][8 * 132];
    __shared__ float Bs[2][8 * 128];

    const int t    = threadIdx.x;
    const int tc   = t & 15;
    const int tr   = t >> 4;
    const int row0 = blockIdx.x * 128;

    // global-load assignments
    const int rA   = t >> 1;            // 0..127
    const int kA   = (t & 1) * 4;       // 0 or 4
    const int rowA = row0 + rA;
    const int rB   = t >> 5;            // 0..7
    const int cB   = (t & 31) * 4;      // 0..124

    float acc[8][8];
#pragma unroll
    for (int i = 0; i < 8; ++i)
#pragma unroll
        for (int j = 0; j < 8; ++j) acc[i][j] = 0.f;

    float4 pa, pb;
    auto gload = [&](int ch) {
        int k0 = ch * 8;
        const float* A = (ch < 16) ? g_agg : g_x;
        const float* W = (ch < 16) ? Wl : Wr;
        int ka = k0 & 127;
        if (rowA < Nn) pa = *(const float4*)(A + (size_t)rowA * Dd + ka + kA);
        else           pa = make_float4(0.f, 0.f, 0.f, 0.f);
        pb = *(const float4*)(W + (size_t)(ka + rB) * Dd + cB);
    };
    auto sstore = [&](int buf) {
        As[buf][(kA + 0) * 132 + rA] = pa.x;
        As[buf][(kA + 1) * 132 + rA] = pa.y;
        As[buf][(kA + 2) * 132 + rA] = pa.z;
        As[buf][(kA + 3) * 132 + rA] = pa.w;
        *(float4*)(&Bs[buf][rB * 128 + cB]) = pb;
    };

    gload(0);
    sstore(0);
    __syncthreads();

    for (int ch = 0; ch < 32; ++ch) {
        int cur = ch & 1;
        if (ch < 31) gload(ch + 1);
#pragma unroll
        for (int kl = 0; kl < 8; ++kl) {
            const float* as = &As[cur][kl * 132 + tr * 8];
            float4 a0 = *(const float4*)(as);
            float4 a1 = *(const float4*)(as + 4);
            const float* bs = &Bs[cur][kl * 128 + tc * 4];
            float4 b0 = *(const float4*)(bs);
            float4 b1 = *(const float4*)(bs + 64);
            float av[8] = {a0.x, a0.y, a0.z, a0.w, a1.x, a1.y, a1.z, a1.w};
            float bv[8] = {b0.x, b0.y, b0.z, b0.w, b1.x, b1.y, b1.z, b1.w};
#pragma unroll
            for (int i = 0; i < 8; ++i)
#pragma unroll
                for (int j = 0; j < 8; ++j)
                    acc[i][j] = fmaf(av[i], bv[j], acc[i][j]);
        }
        if (ch < 31) sstore((ch + 1) & 1);
        __syncthreads();
    }

    // --------------------- Epilogue: bias + relu + residual + LN -----------
    const int c0 = tc * 4;        // cols c0..c0+3
    const int c1 = 64 + tc * 4;   // cols c1..c1+3
    float bb[8], gg[8], bt[8];
    {
        float4 u0 = *(const float4*)(bl + c0);
        float4 u1 = *(const float4*)(bl + c1);
        bb[0]=u0.x; bb[1]=u0.y; bb[2]=u0.z; bb[3]=u0.w;
        bb[4]=u1.x; bb[5]=u1.y; bb[6]=u1.z; bb[7]=u1.w;
        float4 g0 = *(const float4*)(lng + c0);
        float4 g1 = *(const float4*)(lng + c1);
        gg[0]=g0.x; gg[1]=g0.y; gg[2]=g0.z; gg[3]=g0.w;
        gg[4]=g1.x; gg[5]=g1.y; gg[6]=g1.z; gg[7]=g1.w;
        float4 t0 = *(const float4*)(lnb + c0);
        float4 t1 = *(const float4*)(lnb + c1);
        bt[0]=t0.x; bt[1]=t0.y; bt[2]=t0.z; bt[3]=t0.w;
        bt[4]=t1.x; bt[5]=t1.y; bt[6]=t1.z; bt[7]=t1.w;
    }
    float* outp = writeOut ? dout : g_x;

#pragma unroll
    for (int i = 0; i < 8; ++i) {
        int r = row0 + tr * 8 + i;
        float xo[8];
        if (r < Nn) {
            float4 x0 = *(const float4*)(g_x + (size_t)r * Dd + c0);
            float4 x1 = *(const float4*)(g_x + (size_t)r * Dd + c1);
            xo[0]=x0.x; xo[1]=x0.y; xo[2]=x0.z; xo[3]=x0.w;
            xo[4]=x1.x; xo[5]=x1.y; xo[6]=x1.z; xo[7]=x1.w;
        } else {
#pragma unroll
            for (int j = 0; j < 8; ++j) xo[j] = 0.f;
        }
        float s = 0.f, q = 0.f;
#pragma unroll
        for (int j = 0; j < 8; ++j) {
            float h = acc[i][j] + bb[j];
            h = fmaxf(h, 0.f);
            h += xo[j];
            acc[i][j] = h;
            s += h;
            q += h * h;
        }
#pragma unroll
        for (int m = 1; m < 16; m <<= 1) {
            s += __shfl_xor_sync(0xffffffffu, s, m);
            q += __shfl_xor_sync(0xffffffffu, q, m);
        }
        float mean = s * (1.0f / 128.0f);
        float rstd = rsqrtf(q * (1.0f / 128.0f) - mean * mean + EPS_LN);
        if (r < Nn) {
            float4 o0, o1;
            o0.x = (acc[i][0] - mean) * rstd * gg[0] + bt[0];
            o0.y = (acc[i][1] - mean) * rstd * gg[1] + bt[1];
            o0.z = (acc[i][2] - mean) * rstd * gg[2] + bt[2];
            o0.w = (acc[i][3] - mean) * rstd * gg[3] + bt[3];
            o1.x = (acc[i][4] - mean) * rstd * gg[4] + bt[4];
            o1.y = (acc[i][5] - mean) * rstd * gg[5] + bt[5];
            o1.z = (acc[i][6] - mean) * rstd * gg[6] + bt[6];
            o1.w = (acc[i][7] - mean) * rstd * gg[7] + bt[7];
            *(float4*)(outp + (size_t)r * Dd + c0) = o0;
            *(float4*)(outp + (size_t)r * Dd + c1) = o1;
        }
    }
}

// ---------------------------------------------------------------------------
extern "C" void kernel_launch(void* const* d_in, const int* in_sizes, int n_in,
                              void* d_out, int out_size) {
    const float* node_emb  = (const float*)d_in[0];
    const int*   pos       = (const int*)d_in[1];
    const int*   edge      = (const int*)d_in[2];
    const float* pos_table = (const float*)d_in[3];
    const float* Wl        = (const float*)d_in[4];
    const float* bl        = (const float*)d_in[5];
    const float* Wr        = (const float*)d_in[6];
    const float* emb_g     = (const float*)d_in[7];
    const float* emb_b     = (const float*)d_in[8];
    const float* hid_g     = (const float*)d_in[9];
    const float* hid_b     = (const float*)d_in[10];
    float* out = (float*)d_out;

    // embedding + LN
    embed_ln_kernel<<<(Nn * 32 + 255) / 256, 256>>>(node_emb, pos, pos_table,
                                                    emb_g, emb_b);
    // CSR build (reused by all 3 layers)
    zero_deg_kernel<<<(Nn + 255) / 256, 256>>>();
    hist_kernel<<<(Ee + 255) / 256, 256>>>(edge);
    build_rowptr_kernel<<<1, 1024>>>();
    fill_csr_kernel<<<(Ee + 255) / 256, 256>>>(edge);

    const int gemm_blocks = (Nn + 127) / 128;  // 391
    for (int l = 0; l < 3; ++l) {
        aggregate_kernel<<<(Nn * 32 + 255) / 256, 256>>>();
        gemm_ln_kernel<<<gemm_blocks, 256>>>(Wl + (size_t)l * Dd * Dd,
                                             bl + (size_t)l * Dd,
                                             Wr + (size_t)l * Dd * Dd,
                                             hid_g + (size_t)l * Dd,
                                             hid_b + (size_t)l * Dd,
                                             out, l == 2 ? 1 : 0);
    }
}

// round 3
// speedup vs baseline: 1.6263x; 1.1139x over previous
#include <cuda_runtime.h>

#define Nn 50000
#define Dd 128
#define Ee 800000
#define EPS_LN 1e-5f
#define SQRT_D 11.313708498984761f
#define NBLK 196  // ceil(Nn/256)

// Scratch (static device globals — allocation-free per harness rules)
__device__ float g_x[Nn * Dd];    // 25.6 MB
__device__ float g_agg[Nn * Dd];  // 25.6 MB
__device__ int   g_deg[Nn];
__device__ int   g_rp[Nn + 1];
__device__ int   g_cur[Nn];
__device__ int   g_col[Ee];
__device__ int   g_part[NBLK];
__device__ int   g_boff[NBLK];

// ---------------------------------------------------------------------------
// Kernel 1: x = LayerNorm(node_emb * sqrt(D) + pos_table[pos])
// ---------------------------------------------------------------------------
__global__ void embed_ln_kernel(const float* __restrict__ ne,
                                const int* __restrict__ pos,
                                const float* __restrict__ ptab,
                                const float* __restrict__ g,
                                const float* __restrict__ b) {
    int w    = (blockIdx.x * blockDim.x + threadIdx.x) >> 5;
    int lane = threadIdx.x & 31;
    if (w >= Nn) return;
    int p = pos[w];
    float4 nv = *(const float4*)(ne   + (size_t)w * Dd + lane * 4);
    float4 pv = *(const float4*)(ptab + (size_t)p * Dd + lane * 4);
    float v0 = fmaf(nv.x, SQRT_D, pv.x);
    float v1 = fmaf(nv.y, SQRT_D, pv.y);
    float v2 = fmaf(nv.z, SQRT_D, pv.z);
    float v3 = fmaf(nv.w, SQRT_D, pv.w);
    float s = v0 + v1 + v2 + v3;
    float q = v0 * v0 + v1 * v1 + v2 * v2 + v3 * v3;
#pragma unroll
    for (int m = 1; m < 32; m <<= 1) {
        s += __shfl_xor_sync(0xffffffffu, s, m);
        q += __shfl_xor_sync(0xffffffffu, q, m);
    }
    float mean = s * (1.0f / 128.0f);
    float rstd = rsqrtf(q * (1.0f / 128.0f) - mean * mean + EPS_LN);
    float4 gv = *(const float4*)(g + lane * 4);
    float4 bv = *(const float4*)(b + lane * 4);
    float4 o;
    o.x = (v0 - mean) * rstd * gv.x + bv.x;
    o.y = (v1 - mean) * rstd * gv.y + bv.y;
    o.z = (v2 - mean) * rstd * gv.z + bv.z;
    o.w = (v3 - mean) * rstd * gv.w + bv.w;
    *(float4*)(g_x + (size_t)w * Dd + lane * 4) = o;
}

// ---------------------------------------------------------------------------
// CSR build: deg histogram -> fast 3-stage exclusive scan -> column fill
// ---------------------------------------------------------------------------
__global__ void zero_deg_kernel() {
    int i = blockIdx.x * blockDim.x + threadIdx.x;
    if (i < Nn) g_deg[i] = 0;
}

__global__ void hist_kernel(const int* __restrict__ edge) {
    int e = blockIdx.x * blockDim.x + threadIdx.x;
    if (e < Ee) atomicAdd(&g_deg[edge[Ee + e]], 1);
}

// Stage 1: per-block (256-wide) partial sums of deg
__global__ void deg_partials_kernel() {
    __shared__ int sm[256];
    int t = threadIdx.x;
    int i = blockIdx.x * 256 + t;
    int v = (i < Nn) ? g_deg[i] : 0;
    sm[t] = v;
    __syncthreads();
#pragma unroll
    for (int o = 128; o > 0; o >>= 1) {
        if (t < o) sm[t] += sm[t + o];
        __syncthreads();
    }
    if (t == 0) g_part[blockIdx.x] = sm[0];
}

// Stage 2: single block scans the 196 partials -> exclusive block offsets
__global__ void scan_partials_kernel() {
    __shared__ int ts[256];
    int t = threadIdx.x;
    int v = (t < NBLK) ? g_part[t] : 0;
    ts[t] = v;
    __syncthreads();
#pragma unroll
    for (int off = 1; off < 256; off <<= 1) {
        int u = (t >= off) ? ts[t - off] : 0;
        __syncthreads();
        ts[t] += u;
        __syncthreads();
    }
    if (t < NBLK) g_boff[t] = ts[t] - v;  // exclusive
}

// Stage 3: per-block local scan + block offset -> rowptr / cur
__global__ void block_scan_kernel() {
    __shared__ int ts[256];
    int t = threadIdx.x;
    int i = blockIdx.x * 256 + t;
    int v = (i < Nn) ? g_deg[i] : 0;
    ts[t] = v;
    __syncthreads();
#pragma unroll
    for (int off = 1; off < 256; off <<= 1) {
        int u = (t >= off) ? ts[t - off] : 0;
        __syncthreads();
        ts[t] += u;
        __syncthreads();
    }
    if (i < Nn) {
        int excl = ts[t] - v + g_boff[blockIdx.x];
        g_rp[i]  = excl;
        g_cur[i] = excl;
    }
    if (i == 0) g_rp[Nn] = Ee;
}

__global__ void fill_csr_kernel(const int* __restrict__ edge) {
    int e = blockIdx.x * blockDim.x + threadIdx.x;
    if (e < Ee) {
        int src = edge[e];
        int dst = edge[Ee + e];
        int p = atomicAdd(&g_cur[dst], 1);
        g_col[p] = src;
    }
}

// ---------------------------------------------------------------------------
// Aggregate: agg[i] = sum_{j in CSR row i} x[col[j]]   (one warp per row)
// ---------------------------------------------------------------------------
__global__ void aggregate_kernel() {
    int w    = (blockIdx.x * blockDim.x + threadIdx.x) >> 5;
    int lane = threadIdx.x & 31;
    if (w >= Nn) return;
    int beg = g_rp[w];
    int end = g_rp[w + 1];
    float4 a0 = make_float4(0.f, 0.f, 0.f, 0.f);
    float4 a1 = make_float4(0.f, 0.f, 0.f, 0.f);
    int jb = beg;
    while (jb < end) {
        int take = min(32, end - jb);
        int myc = (lane < take) ? __ldg(&g_col[jb + lane]) : 0;
        int u = 0;
        for (; u + 1 < take; u += 2) {
            int s0 = __shfl_sync(0xffffffffu, myc, u);
            int s1 = __shfl_sync(0xffffffffu, myc, u + 1);
            float4 v0 = *(const float4*)(g_x + (size_t)s0 * Dd + lane * 4);
            float4 v1 = *(const float4*)(g_x + (size_t)s1 * Dd + lane * 4);
            a0.x += v0.x; a0.y += v0.y; a0.z += v0.z; a0.w += v0.w;
            a1.x += v1.x; a1.y += v1.y; a1.z += v1.z; a1.w += v1.w;
        }
        if (u < take) {
            int s0 = __shfl_sync(0xffffffffu, myc, u);
            float4 v0 = *(const float4*)(g_x + (size_t)s0 * Dd + lane * 4);
            a0.x += v0.x; a0.y += v0.y; a0.z += v0.z; a0.w += v0.w;
        }
        jb += take;
    }
    float4 o;
    o.x = a0.x + a1.x; o.y = a0.y + a1.y; o.z = a0.z + a1.z; o.w = a0.w + a1.w;
    *(float4*)(g_agg + (size_t)w * Dd + lane * 4) = o;
}

// ---------------------------------------------------------------------------
// Fused dual-GEMM + bias + ReLU + residual + LayerNorm
//   h = relu(agg @ Wl + bl + x @ Wr); x_new = LN(h + x)
// 128x128 block tile, 256 threads, 8x8 thread tile, K=256 in 16 chunks of 16.
// As staged transposed [k][row] with pad-132; double-buffered smem.
// ---------------------------------------------------------------------------
__global__ void __launch_bounds__(256, 2)
gemm_ln_kernel(const float* __restrict__ Wl, const float* __restrict__ bl,
               const float* __restrict__ Wr, const float* __restrict__ lng,
               const float* __restrict__ lnb, float* __restrict__ dout,
               int writeOut) {
    __shared__ float As[2][16 * 132];
    __shared__ float Bs[2][16 * 128];

    const int t    = threadIdx.x;
    const int tc   = t & 15;
    const int tr   = t >> 4;
    const int row0 = blockIdx.x * 128;

    // global-load assignments
    const int rA   = t >> 1;            // 0..127
    const int kA   = (t & 1) * 8;       // 0 or 8
    const int rowA = row0 + rA;
    const int rB   = t >> 4;            // 0..15
    const int cB   = (t & 15) * 8;      // 0..120

    float acc[8][8];
#pragma unroll
    for (int i = 0; i < 8; ++i)
#pragma unroll
        for (int j = 0; j < 8; ++j) acc[i][j] = 0.f;

    float4 pa0, pa1, pb0, pb1;
    auto gload = [&](int ch) {
        const float* A = (ch < 8) ? g_agg : g_x;
        const float* W = (ch < 8) ? Wl : Wr;
        int ka = (ch & 7) * 16;
        if (rowA < Nn) {
            pa0 = *(const float4*)(A + (size_t)rowA * Dd + ka + kA);
            pa1 = *(const float4*)(A + (size_t)rowA * Dd + ka + kA + 4);
        } else {
            pa0 = make_float4(0.f, 0.f, 0.f, 0.f);
            pa1 = make_float4(0.f, 0.f, 0.f, 0.f);
        }
        const float* wrow = W + (size_t)(ka + rB) * Dd + cB;
        pb0 = *(const float4*)(wrow);
        pb1 = *(const float4*)(wrow + 4);
    };
    auto sstore = [&](int buf) {
        As[buf][(kA + 0) * 132 + rA] = pa0.x;
        As[buf][(kA + 1) * 132 + rA] = pa0.y;
        As[buf][(kA + 2) * 132 + rA] = pa0.z;
        As[buf][(kA + 3) * 132 + rA] = pa0.w;
        As[buf][(kA + 4) * 132 + rA] = pa1.x;
        As[buf][(kA + 5) * 132 + rA] = pa1.y;
        As[buf][(kA + 6) * 132 + rA] = pa1.z;
        As[buf][(kA + 7) * 132 + rA] = pa1.w;
        *(float4*)(&Bs[buf][rB * 128 + cB])     = pb0;
        *(float4*)(&Bs[buf][rB * 128 + cB + 4]) = pb1;
    };

    gload(0);
    sstore(0);
    __syncthreads();

    for (int ch = 0; ch < 16; ++ch) {
        int cur = ch & 1;
        if (ch < 15) gload(ch + 1);
#pragma unroll
        for (int kl = 0; kl < 16; ++kl) {
            const float* as = &As[cur][kl * 132 + tr * 8];
            float4 a0 = *(const float4*)(as);
            float4 a1 = *(const float4*)(as + 4);
            const float* bs = &Bs[cur][kl * 128 + tc * 4];
            float4 b0 = *(const float4*)(bs);
            float4 b1 = *(const float4*)(bs + 64);
            float av[8] = {a0.x, a0.y, a0.z, a0.w, a1.x, a1.y, a1.z, a1.w};
            float bv[8] = {b0.x, b0.y, b0.z, b0.w, b1.x, b1.y, b1.z, b1.w};
#pragma unroll
            for (int i = 0; i < 8; ++i)
#pragma unroll
                for (int j = 0; j < 8; ++j)
                    acc[i][j] = fmaf(av[i], bv[j], acc[i][j]);
        }
        if (ch < 15) sstore((ch + 1) & 1);
        __syncthreads();
    }

    // --------------------- Epilogue: bias + relu + residual + LN -----------
    const int c0 = tc * 4;        // cols c0..c0+3
    const int c1 = 64 + tc * 4;   // cols c1..c1+3
    float bb[8], gg[8], bt[8];
    {
        float4 u0 = *(const float4*)(bl + c0);
        float4 u1 = *(const float4*)(bl + c1);
        bb[0]=u0.x; bb[1]=u0.y; bb[2]=u0.z; bb[3]=u0.w;
        bb[4]=u1.x; bb[5]=u1.y; bb[6]=u1.z; bb[7]=u1.w;
        float4 g0 = *(const float4*)(lng + c0);
        float4 g1 = *(const float4*)(lng + c1);
        gg[0]=g0.x; gg[1]=g0.y; gg[2]=g0.z; gg[3]=g0.w;
        gg[4]=g1.x; gg[5]=g1.y; gg[6]=g1.z; gg[7]=g1.w;
        float4 t0 = *(const float4*)(lnb + c0);
        float4 t1 = *(const float4*)(lnb + c1);
        bt[0]=t0.x; bt[1]=t0.y; bt[2]=t0.z; bt[3]=t0.w;
        bt[4]=t1.x; bt[5]=t1.y; bt[6]=t1.z; bt[7]=t1.w;
    }
    float* outp = writeOut ? dout : g_x;

#pragma unroll
    for (int i = 0; i < 8; ++i) {
        int r = row0 + tr * 8 + i;
        float xo[8];
        if (r < Nn) {
            float4 x0 = *(const float4*)(g_x + (size_t)r * Dd + c0);
            float4 x1 = *(const float4*)(g_x + (size_t)r * Dd + c1);
            xo[0]=x0.x; xo[1]=x0.y; xo[2]=x0.z; xo[3]=x0.w;
            xo[4]=x1.x; xo[5]=x1.y; xo[6]=x1.z; xo[7]=x1.w;
        } else {
#pragma unroll
            for (int j = 0; j < 8; ++j) xo[j] = 0.f;
        }
        float s = 0.f, q = 0.f;
#pragma unroll
        for (int j = 0; j < 8; ++j) {
            float h = acc[i][j] + bb[j];
            h = fmaxf(h, 0.f);
            h += xo[j];
            acc[i][j] = h;
            s += h;
            q += h * h;
        }
#pragma unroll
        for (int m = 1; m < 16; m <<= 1) {
            s += __shfl_xor_sync(0xffffffffu, s, m);
            q += __shfl_xor_sync(0xffffffffu, q, m);
        }
        float mean = s * (1.0f / 128.0f);
        float rstd = rsqrtf(q * (1.0f / 128.0f) - mean * mean + EPS_LN);
        if (r < Nn) {
            float4 o0, o1;
            o0.x = (acc[i][0] - mean) * rstd * gg[0] + bt[0];
            o0.y = (acc[i][1] - mean) * rstd * gg[1] + bt[1];
            o0.z = (acc[i][2] - mean) * rstd * gg[2] + bt[2];
            o0.w = (acc[i][3] - mean) * rstd * gg[3] + bt[3];
            o1.x = (acc[i][4] - mean) * rstd * gg[4] + bt[4];
            o1.y = (acc[i][5] - mean) * rstd * gg[5] + bt[5];
            o1.z = (acc[i][6] - mean) * rstd * gg[6] + bt[6];
            o1.w = (acc[i][7] - mean) * rstd * gg[7] + bt[7];
            *(float4*)(outp + (size_t)r * Dd + c0) = o0;
            *(float4*)(outp + (size_t)r * Dd + c1) = o1;
        }
    }
}

// ---------------------------------------------------------------------------
extern "C" void kernel_launch(void* const* d_in, const int* in_sizes, int n_in,
                              void* d_out, int out_size) {
    const float* node_emb  = (const float*)d_in[0];
    const int*   pos       = (const int*)d_in[1];
    const int*   edge      = (const int*)d_in[2];
    const float* pos_table = (const float*)d_in[3];
    const float* Wl        = (const float*)d_in[4];
    const float* bl        = (const float*)d_in[5];
    const float* Wr        = (const float*)d_in[6];
    const float* emb_g     = (const float*)d_in[7];
    const float* emb_b     = (const float*)d_in[8];
    const float* hid_g     = (const float*)d_in[9];
    const float* hid_b     = (const float*)d_in[10];
    float* out = (float*)d_out;

    // embedding + LN
    embed_ln_kernel<<<(Nn * 32 + 255) / 256, 256>>>(node_emb, pos, pos_table,
                                                    emb_g, emb_b);
    // CSR build (reused by all 3 layers)
    zero_deg_kernel<<<NBLK, 256>>>();
    hist_kernel<<<(Ee + 255) / 256, 256>>>(edge);
    deg_partials_kernel<<<NBLK, 256>>>();
    scan_partials_kernel<<<1, 256>>>();
    block_scan_kernel<<<NBLK, 256>>>();
    fill_csr_kernel<<<(Ee + 255) / 256, 256>>>(edge);

    const int gemm_blocks = (Nn + 127) / 128;  // 391
    for (int l = 0; l < 3; ++l) {
        aggregate_kernel<<<(Nn * 32 + 255) / 256, 256>>>();
        gemm_ln_kernel<<<gemm_blocks, 256>>>(Wl + (size_t)l * Dd * Dd,
                                             bl + (size_t)l * Dd,
                                             Wr + (size_t)l * Dd * Dd,
                                             hid_g + (size_t)l * Dd,
                                             hid_b + (size_t)l * Dd,
                                             out, l == 2 ? 1 : 0);
    }
}

// round 4
// speedup vs baseline: 1.7803x; 1.0947x over previous
#include <cuda_runtime.h>

#define Nn 50000
#define Dd 128
#define Ee 800000
#define EPS_LN 1e-5f
#define SQRT_D 11.313708498984761f
#define NBLK 196  // ceil(Nn/256)

// Scratch (static device globals — allocation-free per harness rules)
__device__ float g_x[Nn * Dd];    // 25.6 MB
__device__ float g_agg[Nn * Dd];  // 25.6 MB
__device__ int   g_deg[Nn];
__device__ int   g_rp[Nn + 1];
__device__ int   g_cur[Nn];
__device__ int   g_col[Ee];
__device__ int   g_part[NBLK];
__device__ int   g_boff[NBLK];

// ---------------- packed f32x2 helpers (sm_103a) ---------------------------
__device__ __forceinline__ unsigned long long pack2(float x) {
    unsigned long long r;
    asm("mov.b64 %0, {%1, %1};" : "=l"(r) : "f"(x));
    return r;
}
__device__ __forceinline__ void fma2(unsigned long long& d,
                                     unsigned long long a,
                                     unsigned long long b) {
    asm("fma.rn.f32x2 %0, %1, %2, %0;" : "+l"(d) : "l"(a), "l"(b));
}
__device__ __forceinline__ void unpack2(unsigned long long v, float& lo, float& hi) {
    asm("mov.b64 {%0, %1}, %2;" : "=f"(lo), "=f"(hi) : "l"(v));
}

// ---------------------------------------------------------------------------
// Kernel 1: x = LayerNorm(node_emb * sqrt(D) + pos_table[pos])
// ---------------------------------------------------------------------------
__global__ void embed_ln_kernel(const float* __restrict__ ne,
                                const int* __restrict__ pos,
                                const float* __restrict__ ptab,
                                const float* __restrict__ g,
                                const float* __restrict__ b) {
    int w    = (blockIdx.x * blockDim.x + threadIdx.x) >> 5;
    int lane = threadIdx.x & 31;
    if (w >= Nn) return;
    int p = pos[w];
    float4 nv = *(const float4*)(ne   + (size_t)w * Dd + lane * 4);
    float4 pv = *(const float4*)(ptab + (size_t)p * Dd + lane * 4);
    float v0 = fmaf(nv.x, SQRT_D, pv.x);
    float v1 = fmaf(nv.y, SQRT_D, pv.y);
    float v2 = fmaf(nv.z, SQRT_D, pv.z);
    float v3 = fmaf(nv.w, SQRT_D, pv.w);
    float s = v0 + v1 + v2 + v3;
    float q = v0 * v0 + v1 * v1 + v2 * v2 + v3 * v3;
#pragma unroll
    for (int m = 1; m < 32; m <<= 1) {
        s += __shfl_xor_sync(0xffffffffu, s, m);
        q += __shfl_xor_sync(0xffffffffu, q, m);
    }
    float mean = s * (1.0f / 128.0f);
    float rstd = rsqrtf(q * (1.0f / 128.0f) - mean * mean + EPS_LN);
    float4 gv = *(const float4*)(g + lane * 4);
    float4 bv = *(const float4*)(b + lane * 4);
    float4 o;
    o.x = (v0 - mean) * rstd * gv.x + bv.x;
    o.y = (v1 - mean) * rstd * gv.y + bv.y;
    o.z = (v2 - mean) * rstd * gv.z + bv.z;
    o.w = (v3 - mean) * rstd * gv.w + bv.w;
    *(float4*)(g_x + (size_t)w * Dd + lane * 4) = o;
}

// ---------------------------------------------------------------------------
// CSR build: deg histogram -> 3-stage exclusive scan -> column fill
// ---------------------------------------------------------------------------
__global__ void zero_deg_kernel() {
    int i = blockIdx.x * blockDim.x + threadIdx.x;
    if (i < Nn) g_deg[i] = 0;
}

__global__ void hist_kernel(const int* __restrict__ edge) {
    int e = blockIdx.x * blockDim.x + threadIdx.x;
    if (e < Ee) atomicAdd(&g_deg[edge[Ee + e]], 1);
}

__global__ void deg_partials_kernel() {
    __shared__ int sm[256];
    int t = threadIdx.x;
    int i = blockIdx.x * 256 + t;
    int v = (i < Nn) ? g_deg[i] : 0;
    sm[t] = v;
    __syncthreads();
#pragma unroll
    for (int o = 128; o > 0; o >>= 1) {
        if (t < o) sm[t] += sm[t + o];
        __syncthreads();
    }
    if (t == 0) g_part[blockIdx.x] = sm[0];
}

__global__ void scan_partials_kernel() {
    __shared__ int ts[256];
    int t = threadIdx.x;
    int v = (t < NBLK) ? g_part[t] : 0;
    ts[t] = v;
    __syncthreads();
#pragma unroll
    for (int off = 1; off < 256; off <<= 1) {
        int u = (t >= off) ? ts[t - off] : 0;
        __syncthreads();
        ts[t] += u;
        __syncthreads();
    }
    if (t < NBLK) g_boff[t] = ts[t] - v;  // exclusive
}

__global__ void block_scan_kernel() {
    __shared__ int ts[256];
    int t = threadIdx.x;
    int i = blockIdx.x * 256 + t;
    int v = (i < Nn) ? g_deg[i] : 0;
    ts[t] = v;
    __syncthreads();
#pragma unroll
    for (int off = 1; off < 256; off <<= 1) {
        int u = (t >= off) ? ts[t - off] : 0;
        __syncthreads();
        ts[t] += u;
        __syncthreads();
    }
    if (i < Nn) {
        int excl = ts[t] - v + g_boff[blockIdx.x];
        g_rp[i]  = excl;
        g_cur[i] = excl;
    }
    if (i == 0) g_rp[Nn] = Ee;
}

__global__ void fill_csr_kernel(const int* __restrict__ edge) {
    int e = blockIdx.x * blockDim.x + threadIdx.x;
    if (e < Ee) {
        int src = edge[e];
        int dst = edge[Ee + e];
        int p = atomicAdd(&g_cur[dst], 1);
        g_col[p] = src;
    }
}

// ---------------------------------------------------------------------------
// Aggregate: agg[i] = sum_{j in CSR row i} x[col[j]]   (one warp per row)
// ---------------------------------------------------------------------------
__global__ void aggregate_kernel() {
    int w    = (blockIdx.x * blockDim.x + threadIdx.x) >> 5;
    int lane = threadIdx.x & 31;
    if (w >= Nn) return;
    int beg = g_rp[w];
    int end = g_rp[w + 1];
    float4 a0 = make_float4(0.f, 0.f, 0.f, 0.f);
    float4 a1 = make_float4(0.f, 0.f, 0.f, 0.f);
    int jb = beg;
    while (jb < end) {
        int take = min(32, end - jb);
        int myc = (lane < take) ? __ldg(&g_col[jb + lane]) : 0;
        int u = 0;
        for (; u + 1 < take; u += 2) {
            int s0 = __shfl_sync(0xffffffffu, myc, u);
            int s1 = __shfl_sync(0xffffffffu, myc, u + 1);
            float4 v0 = *(const float4*)(g_x + (size_t)s0 * Dd + lane * 4);
            float4 v1 = *(const float4*)(g_x + (size_t)s1 * Dd + lane * 4);
            a0.x += v0.x; a0.y += v0.y; a0.z += v0.z; a0.w += v0.w;
            a1.x += v1.x; a1.y += v1.y; a1.z += v1.z; a1.w += v1.w;
        }
        if (u < take) {
            int s0 = __shfl_sync(0xffffffffu, myc, u);
            float4 v0 = *(const float4*)(g_x + (size_t)s0 * Dd + lane * 4);
            a0.x += v0.x; a0.y += v0.y; a0.z += v0.z; a0.w += v0.w;
        }
        jb += take;
    }
    float4 o;
    o.x = a0.x + a1.x; o.y = a0.y + a1.y; o.z = a0.z + a1.z; o.w = a0.w + a1.w;
    *(float4*)(g_agg + (size_t)w * Dd + lane * 4) = o;
}

// ---------------------------------------------------------------------------
// Fused dual-GEMM + bias + ReLU + residual + LayerNorm (packed f32x2 FMA)
//   h = relu(agg @ Wl + bl + x @ Wr); x_new = LN(h + x)
// 128x128 block tile, 256 threads, 8x8 thread tile, K=256 in 32 chunks of 8.
// acc held as 8x4 packed f32x2 (column pairs). A broadcast packed per k.
// ---------------------------------------------------------------------------
__global__ void __launch_bounds__(256, 2)
gemm_ln_kernel(const float* __restrict__ Wl, const float* __restrict__ bl,
               const float* __restrict__ Wr, const float* __restrict__ lng,
               const float* __restrict__ lnb, float* __restrict__ dout,
               int writeOut) {
    __shared__ float As[2][8 * 132];
    __shared__ float Bs[2][8 * 128];

    const int t    = threadIdx.x;
    const int tc   = t & 15;
    const int tr   = t >> 4;
    const int row0 = blockIdx.x * 128;

    // global-load assignments
    const int rA   = t >> 1;            // 0..127
    const int kA   = (t & 1) * 4;       // 0 or 4
    const int rowA = row0 + rA;
    const int rB   = t >> 5;            // 0..7
    const int cB   = (t & 31) * 4;      // 0..124

    unsigned long long acc2[8][4];
#pragma unroll
    for (int i = 0; i < 8; ++i)
#pragma unroll
        for (int j = 0; j < 4; ++j) acc2[i][j] = 0ull;

    float4 pa, pb;
    auto gload = [&](int ch) {
        int k0 = ch * 8;
        const float* A = (ch < 16) ? g_agg : g_x;
        const float* W = (ch < 16) ? Wl : Wr;
        int ka = k0 & 127;
        if (rowA < Nn) pa = *(const float4*)(A + (size_t)rowA * Dd + ka + kA);
        else           pa = make_float4(0.f, 0.f, 0.f, 0.f);
        pb = *(const float4*)(W + (size_t)(ka + rB) * Dd + cB);
    };
    auto sstore = [&](int buf) {
        As[buf][(kA + 0) * 132 + rA] = pa.x;
        As[buf][(kA + 1) * 132 + rA] = pa.y;
        As[buf][(kA + 2) * 132 + rA] = pa.z;
        As[buf][(kA + 3) * 132 + rA] = pa.w;
        *(float4*)(&Bs[buf][rB * 128 + cB]) = pb;
    };

    gload(0);
    sstore(0);
    __syncthreads();

    for (int ch = 0; ch < 32; ++ch) {
        int cur = ch & 1;
        if (ch < 31) gload(ch + 1);
#pragma unroll
        for (int kl = 0; kl < 8; ++kl) {
            const float* as = &As[cur][kl * 132 + tr * 8];
            float4 a0 = *(const float4*)(as);
            float4 a1 = *(const float4*)(as + 4);
            const unsigned long long* bs64 =
                (const unsigned long long*)(&Bs[cur][kl * 128 + tc * 4]);
            unsigned long long bv2[4];
            bv2[0] = bs64[0];
            bv2[1] = bs64[1];
            bv2[2] = bs64[32];   // +64 floats
            bv2[3] = bs64[33];
            unsigned long long av2[8];
            av2[0] = pack2(a0.x); av2[1] = pack2(a0.y);
            av2[2] = pack2(a0.z); av2[3] = pack2(a0.w);
            av2[4] = pack2(a1.x); av2[5] = pack2(a1.y);
            av2[6] = pack2(a1.z); av2[7] = pack2(a1.w);
#pragma unroll
            for (int i = 0; i < 8; ++i)
#pragma unroll
                for (int j = 0; j < 4; ++j)
                    fma2(acc2[i][j], av2[i], bv2[j]);
        }
        if (ch < 31) sstore((ch + 1) & 1);
        __syncthreads();
    }

    // --------------------- Epilogue: bias + relu + residual + LN -----------
    const int c0 = tc * 4;        // cols c0..c0+3
    const int c1 = 64 + tc * 4;   // cols c1..c1+3
    float bb[8], gg[8], bt[8];
    {
        float4 u0 = *(const float4*)(bl + c0);
        float4 u1 = *(const float4*)(bl + c1);
        bb[0]=u0.x; bb[1]=u0.y; bb[2]=u0.z; bb[3]=u0.w;
        bb[4]=u1.x; bb[5]=u1.y; bb[6]=u1.z; bb[7]=u1.w;
        float4 g0 = *(const float4*)(lng + c0);
        float4 g1 = *(const float4*)(lng + c1);
        gg[0]=g0.x; gg[1]=g0.y; gg[2]=g0.z; gg[3]=g0.w;
        gg[4]=g1.x; gg[5]=g1.y; gg[6]=g1.z; gg[7]=g1.w;
        float4 t0 = *(const float4*)(lnb + c0);
        float4 t1 = *(const float4*)(lnb + c1);
        bt[0]=t0.x; bt[1]=t0.y; bt[2]=t0.z; bt[3]=t0.w;
        bt[4]=t1.x; bt[5]=t1.y; bt[6]=t1.z; bt[7]=t1.w;
    }
    float* outp = writeOut ? dout : g_x;

#pragma unroll
    for (int i = 0; i < 8; ++i) {
        int r = row0 + tr * 8 + i;
        float hv[8];
        unpack2(acc2[i][0], hv[0], hv[1]);
        unpack2(acc2[i][1], hv[2], hv[3]);
        unpack2(acc2[i][2], hv[4], hv[5]);
        unpack2(acc2[i][3], hv[6], hv[7]);
        float xo[8];
        if (r < Nn) {
            float4 x0 = *(const float4*)(g_x + (size_t)r * Dd + c0);
            float4 x1 = *(const float4*)(g_x + (size_t)r * Dd + c1);
            xo[0]=x0.x; xo[1]=x0.y; xo[2]=x0.z; xo[3]=x0.w;
            xo[4]=x1.x; xo[5]=x1.y; xo[6]=x1.z; xo[7]=x1.w;
        } else {
#pragma unroll
            for (int j = 0; j < 8; ++j) xo[j] = 0.f;
        }
        float s = 0.f, q = 0.f;
#pragma unroll
        for (int j = 0; j < 8; ++j) {
            float h = hv[j] + bb[j];
            h = fmaxf(h, 0.f);
            h += xo[j];
            hv[j] = h;
            s += h;
            q += h * h;
        }
#pragma unroll
        for (int m = 1; m < 16; m <<= 1) {
            s += __shfl_xor_sync(0xffffffffu, s, m);
            q += __shfl_xor_sync(0xffffffffu, q, m);
        }
        float mean = s * (1.0f / 128.0f);
        float rstd = rsqrtf(q * (1.0f / 128.0f) - mean * mean + EPS_LN);
        if (r < Nn) {
            float4 o0, o1;
            o0.x = (hv[0] - mean) * rstd * gg[0] + bt[0];
            o0.y = (hv[1] - mean) * rstd * gg[1] + bt[1];
            o0.z = (hv[2] - mean) * rstd * gg[2] + bt[2];
            o0.w = (hv[3] - mean) * rstd * gg[3] + bt[3];
            o1.x = (hv[4] - mean) * rstd * gg[4] + bt[4];
            o1.y = (hv[5] - mean) * rstd * gg[5] + bt[5];
            o1.z = (hv[6] - mean) * rstd * gg[6] + bt[6];
            o1.w = (hv[7] - mean) * rstd * gg[7] + bt[7];
            *(float4*)(outp + (size_t)r * Dd + c0) = o0;
            *(float4*)(outp + (size_t)r * Dd + c1) = o1;
        }
    }
}

// ---------------------------------------------------------------------------
extern "C" void kernel_launch(void* const* d_in, const int* in_sizes, int n_in,
                              void* d_out, int out_size) {
    const float* node_emb  = (const float*)d_in[0];
    const int*   pos       = (const int*)d_in[1];
    const int*   edge      = (const int*)d_in[2];
    const float* pos_table = (const float*)d_in[3];
    const float* Wl        = (const float*)d_in[4];
    const float* bl        = (const float*)d_in[5];
    const float* Wr        = (const float*)d_in[6];
    const float* emb_g     = (const float*)d_in[7];
    const float* emb_b     = (const float*)d_in[8];
    const float* hid_g     = (const float*)d_in[9];
    const float* hid_b     = (const float*)d_in[10];
    float* out = (float*)d_out;

    // embedding + LN
    embed_ln_kernel<<<(Nn * 32 + 255) / 256, 256>>>(node_emb, pos, pos_table,
                                                    emb_g, emb_b);
    // CSR build (reused by all 3 layers)
    zero_deg_kernel<<<NBLK, 256>>>();
    hist_kernel<<<(Ee + 255) / 256, 256>>>(edge);
    deg_partials_kernel<<<NBLK, 256>>>();
    scan_partials_kernel<<<1, 256>>>();
    block_scan_kernel<<<NBLK, 256>>>();
    fill_csr_kernel<<<(Ee + 255) / 256, 256>>>(edge);

    const int gemm_blocks = (Nn + 127) / 128;  // 391
    for (int l = 0; l < 3; ++l) {
        aggregate_kernel<<<(Nn * 32 + 255) / 256, 256>>>();
        gemm_ln_kernel<<<gemm_blocks, 256>>>(Wl + (size_t)l * Dd * Dd,
                                             bl + (size_t)l * Dd,
                                             Wr + (size_t)l * Dd * Dd,
                                             hid_g + (size_t)l * Dd,
                                             hid_b + (size_t)l * Dd,
                                             out, l == 2 ? 1 : 0);
    }
}